// round 8
// baseline (speedup 1.0000x reference)
#include <cuda_runtime.h>
#include <cstdint>

// Problem constants
#define B  2
#define L  8192
#define D  1024
#define NFFT 16384
#define TPB 1024
#define NTW (NFFT / 4)                        // 4096 twiddles = 32 KB (L1-resident)
#define NPAD (NFFT + NFFT/16)
#define SMEM_BYTES (NPAD * sizeof(float2))    // 139264 B

// ---------------- device scratch ----------------
__device__ float  g_xt[(size_t)B * D * L];
__device__ float  g_ht[(size_t)D * L];
__device__ float2 g_hf[(size_t)D * NFFT];
__device__ float  g_yt[(size_t)B * D * L];
__device__ float2 g_tw[NTW];

// ---------------- helpers ----------------
__device__ __forceinline__ int pidx(int a) { return a + (a >> 4); }

__device__ __forceinline__ float2 cmul(float2 a, float2 b) {
    return make_float2(fmaf(a.x, b.x, -a.y * b.y),
                       fmaf(a.x, b.y,  a.y * b.x));
}
__device__ __forceinline__ float2 cadd(float2 a, float2 b) { return make_float2(a.x + b.x, a.y + b.y); }
__device__ __forceinline__ float2 csub(float2 a, float2 b) { return make_float2(a.x - b.x, a.y - b.y); }

__device__ __forceinline__ void bf4_dif(float2& a0, float2& a1, float2& a2, float2& a3) {
    float2 t0 = cadd(a0, a2), t1 = csub(a0, a2);
    float2 t2 = cadd(a1, a3), t3 = csub(a1, a3);
    a0 = cadd(t0, t2);
    a2 = csub(t0, t2);
    a1 = make_float2(t1.x + t3.y, t1.y - t3.x);  // t1 - i*t3
    a3 = make_float2(t1.x - t3.y, t1.y + t3.x);  // t1 + i*t3
}
__device__ __forceinline__ void bf4_dit(float2& a0, float2& a1, float2& a2, float2& a3) {
    float2 t0 = cadd(a0, a2), t1 = csub(a0, a2);
    float2 t2 = cadd(a1, a3), t3 = csub(a1, a3);
    a0 = cadd(t0, t2);
    a2 = csub(t0, t2);
    a1 = make_float2(t1.x - t3.y, t1.y + t3.x);  // t1 + i*t3
    a3 = make_float2(t1.x + t3.y, t1.y - t3.x);  // t1 - i*t3
}

// base-4 digit reversal of 14 bits: bit-reverse then swap adjacent bit pairs
__device__ __forceinline__ int rev4_14(int x) {
    unsigned y = __brev((unsigned)x) >> 18;
    return (int)(((y & 0x2AAAu) >> 1) | ((y & 0x1555u) << 1));
}

// ---------------- init: twiddles ----------------
__global__ void init_kernel() {
    int k = blockIdx.x * blockDim.x + threadIdx.x;
    if (k < NTW) {
        float s, c;
        sincospif(-2.0f * (float)k / (float)NFFT, &s, &c);
        g_tw[k] = make_float2(c, s);
    }
}

// ---------------- vectorized tiled transpose: in[R][C] -> out[C][R], batched over z ----
// Tile: 32 rows x 128 cols. block (32,8). C % 128 == 0, R % 32 == 0.
#define TTW 132   // padded tile row width in floats (128 + 4); 528 B, 16B-aligned
__global__ void transpose_kernel(const float* __restrict__ in, float* __restrict__ out,
                                 int R, int C) {
    __shared__ float t[32 * TTW];
    const size_t zoff = (size_t)blockIdx.z * (size_t)R * (size_t)C;
    const int cbase = blockIdx.x * 128;
    const int rbase = blockIdx.y * 32;
    const int x = threadIdx.x, y = threadIdx.y;

    // load phase: LDG.128 coalesced, STS.128 lane-consecutive (conflict-free)
    const float4* __restrict__ in4 = (const float4*)(in + zoff);
#pragma unroll
    for (int it = 0; it < 4; it++) {
        const int r = y + 8 * it;
        float4 v = in4[((size_t)(rbase + r) * C + cbase) / 4 + x];
        *(float4*)&t[r * TTW + 4 * x] = v;
    }
    __syncthreads();

    // store phase: LDS.32 lane-consecutive (conflict-free), STG.128
    float* __restrict__ outz = out + zoff;
#pragma unroll
    for (int it = 0; it < 4; it++) {
        const int c_loc = x + 32 * it;
        float4 v;
        v.x = t[(4 * y + 0) * TTW + c_loc];
        v.y = t[(4 * y + 1) * TTW + c_loc];
        v.z = t[(4 * y + 2) * TTW + c_loc];
        v.w = t[(4 * y + 3) * TTW + c_loc];
        *(float4*)&outz[(size_t)(cbase + c_loc) * R + rbase + 4 * y] = v;
    }
}

// ---------------- fused first fwd stage (14+12) straight from gmem ----------------
__device__ __forceinline__ void stageA_fwd(const float* __restrict__ row0,
                                           const float* __restrict__ row1,
                                           float2* sd, int tid) {
    float2 v[4][4];
    const int pb = tid + (tid >> 4);
#pragma unroll
    for (int r = 0; r < 4; r++) {
        const int i0 = tid + r * 1024;          // s=0
        const int i1 = i0 + 4096;               // s=1
        float2 a0 = make_float2(__ldcs(row0 + i0), __ldcs(row1 + i0));
        float2 a1 = make_float2(__ldcs(row0 + i1), __ldcs(row1 + i1));
        // bf4_dif with a2=a3=0:
        float2 X0 = cadd(a0, a1);
        float2 X2 = csub(a0, a1);
        float2 X1 = make_float2(a0.x + a1.y, a0.y - a1.x);  // a0 - i*a1
        float2 X3 = make_float2(a0.x - a1.y, a0.y + a1.x);  // a0 + i*a1
        float2 w  = g_tw[tid + r * 1024];       // S=1
        float2 w2 = cmul(w, w);
        float2 w3 = cmul(w2, w);
        v[r][0] = X0;
        v[r][1] = cmul(X1, w);
        v[r][2] = cmul(X2, w2);
        v[r][3] = cmul(X3, w3);
    }
    {
        float2 wb  = g_tw[4 * tid];
        float2 wb2 = cmul(wb, wb);
        float2 wb3 = cmul(wb2, wb);
#pragma unroll
        for (int s = 0; s < 4; s++) {
            bf4_dif(v[0][s], v[1][s], v[2][s], v[3][s]);
            v[1][s] = cmul(v[1][s], wb);
            v[2][s] = cmul(v[2][s], wb2);
            v[3][s] = cmul(v[3][s], wb3);
        }
    }
#pragma unroll
    for (int r = 0; r < 4; r++)
#pragma unroll
        for (int s = 0; s < 4; s++) {
            const int off = r * 1024 + s * 4096;
            sd[pb + off + (off >> 4)] = v[r][s];
        }
}

// ---------------- combined DIF stages (LS, LS-2), smem in/out ----------------
template<int LS>
__device__ __forceinline__ void dif_pair(float2* sd, int tid) {
    constexpr int Q2 = 1 << (LS - 4);
    constexpr int Q  = 1 << (LS - 2);
    constexpr int S  = 1 << (14 - LS);
    __syncthreads();
    const int j2 = tid & (Q2 - 1);
    const int g  = tid >> (LS - 4);
    const int base = (g << LS) + j2;
    const int pb = base + (base >> 4);
    float2 v[4][4];
#pragma unroll
    for (int r = 0; r < 4; r++)
#pragma unroll
        for (int s = 0; s < 4; s++) {
            const int off = r * Q2 + s * Q;
            v[r][s] = sd[pb + off + (off >> 4)];
        }
#pragma unroll
    for (int r = 0; r < 4; r++) {
        bf4_dif(v[r][0], v[r][1], v[r][2], v[r][3]);
        float2 w  = g_tw[(j2 + r * Q2) * S];
        float2 w2 = cmul(w, w);
        float2 w3 = cmul(w2, w);
        v[r][1] = cmul(v[r][1], w);
        v[r][2] = cmul(v[r][2], w2);
        v[r][3] = cmul(v[r][3], w3);
    }
    {
        float2 wb  = g_tw[j2 * (4 * S)];
        float2 wb2 = cmul(wb, wb);
        float2 wb3 = cmul(wb2, wb);
#pragma unroll
        for (int s = 0; s < 4; s++) {
            bf4_dif(v[0][s], v[1][s], v[2][s], v[3][s]);
            v[1][s] = cmul(v[1][s], wb);
            v[2][s] = cmul(v[2][s], wb2);
            v[3][s] = cmul(v[3][s], wb3);
        }
    }
#pragma unroll
    for (int r = 0; r < 4; r++)
#pragma unroll
        for (int s = 0; s < 4; s++) {
            const int off = r * Q2 + s * Q;
            sd[pb + off + (off >> 4)] = v[r][s];
        }
}

// final DIF stage ls=2 (hfft only)
__device__ __forceinline__ void dif_last(float2* sd, int tid) {
    __syncthreads();
#pragma unroll
    for (int tt = 0; tt < (NFFT / 4) / TPB; ++tt) {
        int t = tid + tt * TPB;
        int pb = 4 * t + (t >> 2);
        float2 a0 = sd[pb + 0];
        float2 a1 = sd[pb + 1];
        float2 a2 = sd[pb + 2];
        float2 a3 = sd[pb + 3];
        bf4_dif(a0, a1, a2, a3);
        sd[pb + 0] = a0;
        sd[pb + 1] = a1;
        sd[pb + 2] = a2;
        sd[pb + 3] = a3;
    }
}

// combined DIT stages (LSA, LSA+2), smem in/out
template<int LSA>
__device__ __forceinline__ void dit_pair(float2* sd, int tid) {
    constexpr int QA   = 1 << (LSA - 2);
    constexpr int SA   = 1 << (14 - LSA);
    constexpr int QB   = 1 << LSA;
    constexpr int SB   = SA >> 2;
    constexpr int LENB = 1 << (LSA + 2);
    __syncthreads();
    const int j = tid & (QA - 1);
    const int G = tid >> (LSA - 2);
    const int base = G * LENB + j;
    const int pb = base + (base >> 4);
    float2 v[4][4];
#pragma unroll
    for (int r = 0; r < 4; r++)
#pragma unroll
        for (int s = 0; s < 4; s++) {
            const int off = r * QA + s * QB;
            v[r][s] = sd[pb + off + (off >> 4)];
        }
    {
        float2 w   = g_tw[j * SA];
        float2 wc  = make_float2(w.x, -w.y);
        float2 wc2 = cmul(wc, wc);
        float2 wc3 = cmul(wc2, wc);
#pragma unroll
        for (int s = 0; s < 4; s++) {
            v[1][s] = cmul(v[1][s], wc);
            v[2][s] = cmul(v[2][s], wc2);
            v[3][s] = cmul(v[3][s], wc3);
            bf4_dit(v[0][s], v[1][s], v[2][s], v[3][s]);
        }
    }
#pragma unroll
    for (int r = 0; r < 4; r++) {
        float2 w   = g_tw[(j + r * QA) * SB];
        float2 wc  = make_float2(w.x, -w.y);
        float2 wc2 = cmul(wc, wc);
        float2 wc3 = cmul(wc2, wc);
        v[r][1] = cmul(v[r][1], wc);
        v[r][2] = cmul(v[r][2], wc2);
        v[r][3] = cmul(v[r][3], wc3);
        bf4_dit(v[r][0], v[r][1], v[r][2], v[r][3]);
    }
#pragma unroll
    for (int r = 0; r < 4; r++)
#pragma unroll
        for (int s = 0; s < 4; s++) {
            const int off = r * QA + s * QB;
            sd[pb + off + (off >> 4)] = v[r][s];
        }
}

// ---------------- H spectra: TWO channels per block via Hermitian split ----------------
__global__ __launch_bounds__(TPB, 1)
void hfft_kernel() {
    extern __shared__ float2 sd[];
    const int tid = threadIdx.x;
    const int d0  = 2 * blockIdx.x;
    const int d1  = d0 + 1;

    stageA_fwd(g_ht + (size_t)d0 * L, g_ht + (size_t)d1 * L, sd, tid);
    dif_pair<10>(sd, tid);
    dif_pair<6>(sd, tid);
    dif_last(sd, tid);
    __syncthreads();

    float2* __restrict__ hf0 = g_hf + (size_t)d0 * NFFT;
    float2* __restrict__ hf1 = g_hf + (size_t)d1 * NFFT;
#pragma unroll
    for (int tt = 0; tt < NFFT / TPB; ++tt) {
        int p = tid + tt * TPB;
        int q = rev4_14((NFFT - rev4_14(p)) & (NFFT - 1));
        float2 zp = sd[p + (p >> 4)];
        float2 zq = sd[q + (q >> 4)];
        // H0 = (zp + conj(zq))/2 ; H1 = -i*(zp - conj(zq))/2
        hf0[p] = make_float2(0.5f * (zp.x + zq.x), 0.5f * (zp.y - zq.y));
        hf1[p] = make_float2(0.5f * (zp.y + zq.y), 0.5f * (zq.x - zp.x));
    }
}

// ---------------- conv: one channel per block, both batches packed re/im ----------------
__global__ __launch_bounds__(TPB, 1)
void conv_kernel(const float* __restrict__ bias) {
    extern __shared__ float2 sd[];
    const int tid = threadIdx.x;
    const int d   = blockIdx.x;

    // Prefetch this block's H spectrum into L2 (used in the fused middle, ~3 stages away).
    const float2* __restrict__ hf = g_hf + (size_t)d * NFFT;
#pragma unroll
    for (int tt = 0; tt < (NFFT / 4) / TPB; ++tt) {
        const char* pfa = (const char*)(hf + 4 * (tid + tt * TPB));
        asm volatile("prefetch.global.L2 [%0];" :: "l"(pfa));
    }

    // fwd: fused first stage from gmem, then two smem pair-stages
    stageA_fwd(g_xt + (size_t)d * L, g_xt + (size_t)(D + d) * L, sd, tid);
    dif_pair<10>(sd, tid);
    dif_pair<6>(sd, tid);

    // fused: dif_last + pointwise *H + dit_first  (all on slots 4t..4t+3)
    __syncthreads();
    const float4* __restrict__ hf4 = (const float4*)hf;
#pragma unroll
    for (int tt = 0; tt < (NFFT / 4) / TPB; ++tt) {
        int t = tid + tt * TPB;
        int pb = 4 * t + (t >> 2);
        float2 a0 = sd[pb + 0];
        float2 a1 = sd[pb + 1];
        float2 a2 = sd[pb + 2];
        float2 a3 = sd[pb + 3];
        bf4_dif(a0, a1, a2, a3);
        float4 hA = __ldcs(hf4 + 2 * t);
        float4 hB = __ldcs(hf4 + 2 * t + 1);
        a0 = cmul(a0, make_float2(hA.x, hA.y));
        a1 = cmul(a1, make_float2(hA.z, hA.w));
        a2 = cmul(a2, make_float2(hB.x, hB.y));
        a3 = cmul(a3, make_float2(hB.z, hB.w));
        bf4_dit(a0, a1, a2, a3);
        sd[pb + 0] = a0;
        sd[pb + 1] = a1;
        sd[pb + 2] = a2;
        sd[pb + 3] = a3;
    }

    dit_pair<4>(sd, tid);
    dit_pair<8>(sd, tid);

    // fused final inverse stage (12+14): smem -> registers -> gmem (keep idx < L only)
    __syncthreads();
    {
        const int pb = tid + (tid >> 4);
        float2 v[4][4];
#pragma unroll
        for (int r = 0; r < 4; r++)
#pragma unroll
            for (int s = 0; s < 4; s++) {
                const int off = r * 1024 + s * 4096;
                v[r][s] = sd[pb + off + (off >> 4)];
            }
        // level A = stage 12: conj twiddles idx 4*tid
        {
            float2 w   = g_tw[4 * tid];
            float2 wc  = make_float2(w.x, -w.y);
            float2 wc2 = cmul(wc, wc);
            float2 wc3 = cmul(wc2, wc);
#pragma unroll
            for (int s = 0; s < 4; s++) {
                v[1][s] = cmul(v[1][s], wc);
                v[2][s] = cmul(v[2][s], wc2);
                v[3][s] = cmul(v[3][s], wc3);
                bf4_dit(v[0][s], v[1][s], v[2][s], v[3][s]);
            }
        }
        // level B = stage 14: conj twiddles idx tid + r*1024, butterfly over s
        const float invN = 1.0f / (float)NFFT;
        const float bd = bias[d];
        float* __restrict__ y0 = g_yt + (size_t)d * L;
        float* __restrict__ y1 = g_yt + (size_t)(D + d) * L;
#pragma unroll
        for (int r = 0; r < 4; r++) {
            float2 w   = g_tw[tid + r * 1024];
            float2 wc  = make_float2(w.x, -w.y);
            float2 wc2 = cmul(wc, wc);
            float2 wc3 = cmul(wc2, wc);
            v[r][1] = cmul(v[r][1], wc);
            v[r][2] = cmul(v[r][2], wc2);
            v[r][3] = cmul(v[r][3], wc3);
            bf4_dit(v[r][0], v[r][1], v[r][2], v[r][3]);
            // outputs with natural index < L are s in {0,1}
#pragma unroll
            for (int s = 0; s < 2; s++) {
                const int idx = tid + r * 1024 + s * 4096;
                y0[idx] = fmaf(v[r][s].x, invN, bd);
                y1[idx] = fmaf(v[r][s].y, invN, bd);
            }
        }
    }
}

// ---------------- launch ----------------
extern "C" void kernel_launch(void* const* d_in, const int* in_sizes, int n_in,
                              void* d_out, int out_size) {
    const float* x    = (const float*)d_in[0];
    const float* h    = (const float*)d_in[1];
    const float* bias = (const float*)d_in[2];
    float* out = (float*)d_out;

    void *xt_p, *ht_p, *yt_p;
    cudaGetSymbolAddress(&xt_p, g_xt);
    cudaGetSymbolAddress(&ht_p, g_ht);
    cudaGetSymbolAddress(&yt_p, g_yt);

    cudaFuncSetAttribute(hfft_kernel, cudaFuncAttributeMaxDynamicSharedMemorySize, SMEM_BYTES);
    cudaFuncSetAttribute(conv_kernel, cudaFuncAttributeMaxDynamicSharedMemorySize, SMEM_BYTES);

    init_kernel<<<8, 512>>>();
    // x: [L][D] per batch -> [D][L]
    transpose_kernel<<<dim3(D / 128, L / 32, B), dim3(32, 8)>>>(x, (float*)xt_p, L, D);
    // h: [L][D] -> [D][L]
    transpose_kernel<<<dim3(D / 128, L / 32, 1), dim3(32, 8)>>>(h, (float*)ht_p, L, D);
    hfft_kernel<<<D / 2, TPB, SMEM_BYTES>>>();
    conv_kernel<<<D, TPB, SMEM_BYTES>>>(bias);
    // y: [D][L] per batch -> [L][D]
    transpose_kernel<<<dim3(L / 128, D / 32, B), dim3(32, 8)>>>((const float*)yt_p, out, D, L);
}

// round 11
// speedup vs baseline: 1.1172x; 1.1172x over previous
#include <cuda_runtime.h>
#include <cuda_fp16.h>
#include <cstdint>

// Problem constants
#define B  2
#define L  8192
#define D  1024
#define NFFT 16384
#define TPB 1024
#define NTW (NFFT / 4)                        // 4096 twiddles = 32 KB (L1-resident)
#define NPAD (NFFT + NFFT/16)
#define SMEM_BYTES (NPAD * sizeof(float2))    // 139264 B

// ---------------- device scratch ----------------
__device__ float   g_xt[(size_t)B * D * L];
__device__ float   g_ht[(size_t)D * L];
__device__ __half2 g_hfh[(size_t)D * NFFT];   // H spectrum, fp16 complex (digit-reversed order)
__device__ float   g_yt[(size_t)B * D * L];
__device__ float2  g_tw[NTW];

// ---------------- helpers ----------------
__device__ __forceinline__ int pidx(int a) { return a + (a >> 4); }

__device__ __forceinline__ float2 cmul(float2 a, float2 b) {
    return make_float2(fmaf(a.x, b.x, -a.y * b.y),
                       fmaf(a.x, b.y,  a.y * b.x));
}
__device__ __forceinline__ float2 cadd(float2 a, float2 b) { return make_float2(a.x + b.x, a.y + b.y); }
__device__ __forceinline__ float2 csub(float2 a, float2 b) { return make_float2(a.x - b.x, a.y - b.y); }

__device__ __forceinline__ void bf4_dif(float2& a0, float2& a1, float2& a2, float2& a3) {
    float2 t0 = cadd(a0, a2), t1 = csub(a0, a2);
    float2 t2 = cadd(a1, a3), t3 = csub(a1, a3);
    a0 = cadd(t0, t2);
    a2 = csub(t0, t2);
    a1 = make_float2(t1.x + t3.y, t1.y - t3.x);  // t1 - i*t3
    a3 = make_float2(t1.x - t3.y, t1.y + t3.x);  // t1 + i*t3
}
__device__ __forceinline__ void bf4_dit(float2& a0, float2& a1, float2& a2, float2& a3) {
    float2 t0 = cadd(a0, a2), t1 = csub(a0, a2);
    float2 t2 = cadd(a1, a3), t3 = csub(a1, a3);
    a0 = cadd(t0, t2);
    a2 = csub(t0, t2);
    a1 = make_float2(t1.x - t3.y, t1.y + t3.x);  // t1 + i*t3
    a3 = make_float2(t1.x + t3.y, t1.y - t3.x);  // t1 - i*t3
}

// base-4 digit reversal of 14 bits: bit-reverse then swap adjacent bit pairs
__device__ __forceinline__ int rev4_14(int x) {
    unsigned y = __brev((unsigned)x) >> 18;
    return (int)(((y & 0x2AAAu) >> 1) | ((y & 0x1555u) << 1));
}

// ---------------- init: twiddles ----------------
__global__ void init_kernel() {
    int k = blockIdx.x * blockDim.x + threadIdx.x;
    if (k < NTW) {
        float s, c;
        sincospif(-2.0f * (float)k / (float)NFFT, &s, &c);
        g_tw[k] = make_float2(c, s);
    }
}

// ---------------- vectorized tiled transpose: in[R][C] -> out[C][R], batched over z ----
// Tile: 32 rows x 128 cols. block (32,8). C % 128 == 0, R % 32 == 0.
#define TTW 132   // padded tile row width in floats (128 + 4); 528 B, 16B-aligned
__global__ void transpose_kernel(const float* __restrict__ in, float* __restrict__ out,
                                 int R, int C) {
    __shared__ float t[32 * TTW];
    const size_t zoff = (size_t)blockIdx.z * (size_t)R * (size_t)C;
    const int cbase = blockIdx.x * 128;
    const int rbase = blockIdx.y * 32;
    const int x = threadIdx.x, y = threadIdx.y;

    // load phase: LDG.128 coalesced, STS.128 lane-consecutive (conflict-free)
    const float4* __restrict__ in4 = (const float4*)(in + zoff);
#pragma unroll
    for (int it = 0; it < 4; it++) {
        const int r = y + 8 * it;
        float4 v = in4[((size_t)(rbase + r) * C + cbase) / 4 + x];
        *(float4*)&t[r * TTW + 4 * x] = v;
    }
    __syncthreads();

    // store phase: LDS.32 lane-consecutive (conflict-free), STG.128
    float* __restrict__ outz = out + zoff;
#pragma unroll
    for (int it = 0; it < 4; it++) {
        const int c_loc = x + 32 * it;
        float4 v;
        v.x = t[(4 * y + 0) * TTW + c_loc];
        v.y = t[(4 * y + 1) * TTW + c_loc];
        v.z = t[(4 * y + 2) * TTW + c_loc];
        v.w = t[(4 * y + 3) * TTW + c_loc];
        *(float4*)&outz[(size_t)(cbase + c_loc) * R + rbase + 4 * y] = v;
    }
}

// ---------------- fused first fwd stage (14+12) straight from gmem ----------------
// Upper half (indices >= 8192) is the zero padding: specialized butterfly.
__device__ __forceinline__ void stageA_fwd(const float* __restrict__ row0,
                                           const float* __restrict__ row1,
                                           float2* sd, int tid) {
    float2 v[4][4];
    const int pb = tid + (tid >> 4);
#pragma unroll
    for (int r = 0; r < 4; r++) {
        const int i0 = tid + r * 1024;          // s=0
        const int i1 = i0 + 4096;               // s=1
        float2 a0 = make_float2(__ldcs(row0 + i0), __ldcs(row1 + i0));
        float2 a1 = make_float2(__ldcs(row0 + i1), __ldcs(row1 + i1));
        // bf4_dif with a2=a3=0:
        float2 X0 = cadd(a0, a1);
        float2 X2 = csub(a0, a1);
        float2 X1 = make_float2(a0.x + a1.y, a0.y - a1.x);  // a0 - i*a1
        float2 X3 = make_float2(a0.x - a1.y, a0.y + a1.x);  // a0 + i*a1
        float2 w  = g_tw[tid + r * 1024];       // S=1
        float2 w2 = cmul(w, w);
        float2 w3 = cmul(w2, w);
        v[r][0] = X0;
        v[r][1] = cmul(X1, w);
        v[r][2] = cmul(X2, w2);
        v[r][3] = cmul(X3, w3);
    }
    {
        float2 wb  = g_tw[4 * tid];
        float2 wb2 = cmul(wb, wb);
        float2 wb3 = cmul(wb2, wb);
#pragma unroll
        for (int s = 0; s < 4; s++) {
            bf4_dif(v[0][s], v[1][s], v[2][s], v[3][s]);
            v[1][s] = cmul(v[1][s], wb);
            v[2][s] = cmul(v[2][s], wb2);
            v[3][s] = cmul(v[3][s], wb3);
        }
    }
#pragma unroll
    for (int r = 0; r < 4; r++)
#pragma unroll
        for (int s = 0; s < 4; s++) {
            const int off = r * 1024 + s * 4096;
            sd[pb + off + (off >> 4)] = v[r][s];
        }
}

// ---------------- combined DIF stages (LS, LS-2), smem in/out ----------------
template<int LS>
__device__ __forceinline__ void dif_pair(float2* sd, int tid) {
    constexpr int Q2 = 1 << (LS - 4);
    constexpr int Q  = 1 << (LS - 2);
    constexpr int S  = 1 << (14 - LS);
    __syncthreads();
    const int j2 = tid & (Q2 - 1);
    const int g  = tid >> (LS - 4);
    const int base = (g << LS) + j2;
    const int pb = base + (base >> 4);
    float2 v[4][4];
#pragma unroll
    for (int r = 0; r < 4; r++)
#pragma unroll
        for (int s = 0; s < 4; s++) {
            const int off = r * Q2 + s * Q;
            v[r][s] = sd[pb + off + (off >> 4)];
        }
#pragma unroll
    for (int r = 0; r < 4; r++) {
        bf4_dif(v[r][0], v[r][1], v[r][2], v[r][3]);
        float2 w  = g_tw[(j2 + r * Q2) * S];
        float2 w2 = cmul(w, w);
        float2 w3 = cmul(w2, w);
        v[r][1] = cmul(v[r][1], w);
        v[r][2] = cmul(v[r][2], w2);
        v[r][3] = cmul(v[r][3], w3);
    }
    {
        float2 wb  = g_tw[j2 * (4 * S)];
        float2 wb2 = cmul(wb, wb);
        float2 wb3 = cmul(wb2, wb);
#pragma unroll
        for (int s = 0; s < 4; s++) {
            bf4_dif(v[0][s], v[1][s], v[2][s], v[3][s]);
            v[1][s] = cmul(v[1][s], wb);
            v[2][s] = cmul(v[2][s], wb2);
            v[3][s] = cmul(v[3][s], wb3);
        }
    }
#pragma unroll
    for (int r = 0; r < 4; r++)
#pragma unroll
        for (int s = 0; s < 4; s++) {
            const int off = r * Q2 + s * Q;
            sd[pb + off + (off >> 4)] = v[r][s];
        }
}

// final DIF stage ls=2 (hfft only)
__device__ __forceinline__ void dif_last(float2* sd, int tid) {
    __syncthreads();
#pragma unroll
    for (int tt = 0; tt < (NFFT / 4) / TPB; ++tt) {
        int t = tid + tt * TPB;
        int pb = 4 * t + (t >> 2);
        float2 a0 = sd[pb + 0];
        float2 a1 = sd[pb + 1];
        float2 a2 = sd[pb + 2];
        float2 a3 = sd[pb + 3];
        bf4_dif(a0, a1, a2, a3);
        sd[pb + 0] = a0;
        sd[pb + 1] = a1;
        sd[pb + 2] = a2;
        sd[pb + 3] = a3;
    }
}

// combined DIT stages (LSA, LSA+2), smem in/out
template<int LSA>
__device__ __forceinline__ void dit_pair(float2* sd, int tid) {
    constexpr int QA   = 1 << (LSA - 2);
    constexpr int SA   = 1 << (14 - LSA);
    constexpr int QB   = 1 << LSA;
    constexpr int SB   = SA >> 2;
    constexpr int LENB = 1 << (LSA + 2);
    __syncthreads();
    const int j = tid & (QA - 1);
    const int G = tid >> (LSA - 2);
    const int base = G * LENB + j;
    const int pb = base + (base >> 4);
    float2 v[4][4];
#pragma unroll
    for (int r = 0; r < 4; r++)
#pragma unroll
        for (int s = 0; s < 4; s++) {
            const int off = r * QA + s * QB;
            v[r][s] = sd[pb + off + (off >> 4)];
        }
    {
        float2 w   = g_tw[j * SA];
        float2 wc  = make_float2(w.x, -w.y);
        float2 wc2 = cmul(wc, wc);
        float2 wc3 = cmul(wc2, wc);
#pragma unroll
        for (int s = 0; s < 4; s++) {
            v[1][s] = cmul(v[1][s], wc);
            v[2][s] = cmul(v[2][s], wc2);
            v[3][s] = cmul(v[3][s], wc3);
            bf4_dit(v[0][s], v[1][s], v[2][s], v[3][s]);
        }
    }
#pragma unroll
    for (int r = 0; r < 4; r++) {
        float2 w   = g_tw[(j + r * QA) * SB];
        float2 wc  = make_float2(w.x, -w.y);
        float2 wc2 = cmul(wc, wc);
        float2 wc3 = cmul(wc2, wc);
        v[r][1] = cmul(v[r][1], wc);
        v[r][2] = cmul(v[r][2], wc2);
        v[r][3] = cmul(v[r][3], wc3);
        bf4_dit(v[r][0], v[r][1], v[r][2], v[r][3]);
    }
#pragma unroll
    for (int r = 0; r < 4; r++)
#pragma unroll
        for (int s = 0; s < 4; s++) {
            const int off = r * QA + s * QB;
            sd[pb + off + (off >> 4)] = v[r][s];
        }
}

// ---------------- H spectra: TWO channels per block via Hermitian split, fp16 out ----
__global__ __launch_bounds__(TPB, 1)
void hfft_kernel() {
    extern __shared__ float2 sd[];
    const int tid = threadIdx.x;
    const int d0  = 2 * blockIdx.x;
    const int d1  = d0 + 1;

    stageA_fwd(g_ht + (size_t)d0 * L, g_ht + (size_t)d1 * L, sd, tid);
    dif_pair<10>(sd, tid);
    dif_pair<6>(sd, tid);
    dif_last(sd, tid);
    __syncthreads();

    __half2* __restrict__ hf0 = g_hfh + (size_t)d0 * NFFT;
    __half2* __restrict__ hf1 = g_hfh + (size_t)d1 * NFFT;
#pragma unroll
    for (int tt = 0; tt < NFFT / TPB; ++tt) {
        int p = tid + tt * TPB;
        int q = rev4_14((NFFT - rev4_14(p)) & (NFFT - 1));
        float2 zp = sd[p + (p >> 4)];
        float2 zq = sd[q + (q >> 4)];
        // H0 = (zp + conj(zq))/2 ; H1 = -i*(zp - conj(zq))/2
        hf0[p] = __floats2half2_rn(0.5f * (zp.x + zq.x), 0.5f * (zp.y - zq.y));
        hf1[p] = __floats2half2_rn(0.5f * (zp.y + zq.y), 0.5f * (zq.x - zp.x));
    }
}

// ---------------- conv: one channel per block, both batches packed re/im ----------------
__global__ __launch_bounds__(TPB, 1)
void conv_kernel(const float* __restrict__ bias) {
    extern __shared__ float2 sd[];
    const int tid = threadIdx.x;
    const int d   = blockIdx.x;

    // fwd: fused first stage from gmem, then two smem pair-stages
    stageA_fwd(g_xt + (size_t)d * L, g_xt + (size_t)(D + d) * L, sd, tid);
    dif_pair<10>(sd, tid);
    dif_pair<6>(sd, tid);

    // fused: dif_last + pointwise *H (fp16) + dit_first  (all on slots 4t..4t+3)
    __syncthreads();
    const __half2* __restrict__ hfh = g_hfh + (size_t)d * NFFT;
#pragma unroll
    for (int tt = 0; tt < (NFFT / 4) / TPB; ++tt) {
        int t = tid + tt * TPB;
        int pb = 4 * t + (t >> 2);
        float2 a0 = sd[pb + 0];
        float2 a1 = sd[pb + 1];
        float2 a2 = sd[pb + 2];
        float2 a3 = sd[pb + 3];
        bf4_dif(a0, a1, a2, a3);
        // 4 complex fp16 bins = one 16B load
        uint4 raw = __ldcs((const uint4*)(hfh + 4 * t));
        a0 = cmul(a0, __half22float2(*(const __half2*)&raw.x));
        a1 = cmul(a1, __half22float2(*(const __half2*)&raw.y));
        a2 = cmul(a2, __half22float2(*(const __half2*)&raw.z));
        a3 = cmul(a3, __half22float2(*(const __half2*)&raw.w));
        bf4_dit(a0, a1, a2, a3);
        sd[pb + 0] = a0;
        sd[pb + 1] = a1;
        sd[pb + 2] = a2;
        sd[pb + 3] = a3;
    }

    dit_pair<4>(sd, tid);
    dit_pair<8>(sd, tid);

    // fused final inverse stage (12+14): smem -> registers -> gmem (keep idx < L only)
    __syncthreads();
    {
        const int pb = tid + (tid >> 4);
        float2 v[4][4];
#pragma unroll
        for (int r = 0; r < 4; r++)
#pragma unroll
            for (int s = 0; s < 4; s++) {
                const int off = r * 1024 + s * 4096;
                v[r][s] = sd[pb + off + (off >> 4)];
            }
        // level A = stage 12: conj twiddles idx 4*tid
        {
            float2 w   = g_tw[4 * tid];
            float2 wc  = make_float2(w.x, -w.y);
            float2 wc2 = cmul(wc, wc);
            float2 wc3 = cmul(wc2, wc);
#pragma unroll
            for (int s = 0; s < 4; s++) {
                v[1][s] = cmul(v[1][s], wc);
                v[2][s] = cmul(v[2][s], wc2);
                v[3][s] = cmul(v[3][s], wc3);
                bf4_dit(v[0][s], v[1][s], v[2][s], v[3][s]);
            }
        }
        // level B = stage 14: conj twiddles idx tid + r*1024, butterfly over s
        const float invN = 1.0f / (float)NFFT;
        const float bd = bias[d];
        float* __restrict__ y0 = g_yt + (size_t)d * L;
        float* __restrict__ y1 = g_yt + (size_t)(D + d) * L;
#pragma unroll
        for (int r = 0; r < 4; r++) {
            float2 w   = g_tw[tid + r * 1024];
            float2 wc  = make_float2(w.x, -w.y);
            float2 wc2 = cmul(wc, wc);
            float2 wc3 = cmul(wc2, wc);
            v[r][1] = cmul(v[r][1], wc);
            v[r][2] = cmul(v[r][2], wc2);
            v[r][3] = cmul(v[r][3], wc3);
            bf4_dit(v[r][0], v[r][1], v[r][2], v[r][3]);
            // outputs with natural index < L are s in {0,1}
#pragma unroll
            for (int s = 0; s < 2; s++) {
                const int idx = tid + r * 1024 + s * 4096;
                y0[idx] = fmaf(v[r][s].x, invN, bd);
                y1[idx] = fmaf(v[r][s].y, invN, bd);
            }
        }
    }
}

// ---------------- launch ----------------
extern "C" void kernel_launch(void* const* d_in, const int* in_sizes, int n_in,
                              void* d_out, int out_size) {
    const float* x    = (const float*)d_in[0];
    const float* h    = (const float*)d_in[1];
    const float* bias = (const float*)d_in[2];
    float* out = (float*)d_out;

    void *xt_p, *ht_p, *yt_p;
    cudaGetSymbolAddress(&xt_p, g_xt);
    cudaGetSymbolAddress(&ht_p, g_ht);
    cudaGetSymbolAddress(&yt_p, g_yt);

    cudaFuncSetAttribute(hfft_kernel, cudaFuncAttributeMaxDynamicSharedMemorySize, SMEM_BYTES);
    cudaFuncSetAttribute(conv_kernel, cudaFuncAttributeMaxDynamicSharedMemorySize, SMEM_BYTES);

    init_kernel<<<8, 512>>>();
    // x: [L][D] per batch -> [D][L]
    transpose_kernel<<<dim3(D / 128, L / 32, B), dim3(32, 8)>>>(x, (float*)xt_p, L, D);
    // h: [L][D] -> [D][L]
    transpose_kernel<<<dim3(D / 128, L / 32, 1), dim3(32, 8)>>>(h, (float*)ht_p, L, D);
    hfft_kernel<<<D / 2, TPB, SMEM_BYTES>>>();
    conv_kernel<<<D, TPB, SMEM_BYTES>>>(bias);
    // y: [D][L] per batch -> [L][D]
    transpose_kernel<<<dim3(L / 128, D / 32, B), dim3(32, 8)>>>((const float*)yt_p, out, D, L);
}

// round 12
// speedup vs baseline: 1.1651x; 1.0428x over previous
#include <cuda_runtime.h>
#include <cuda_fp16.h>
#include <cstdint>

// Problem constants
#define B  2
#define L  8192
#define D  1024
#define NFFT 16384
#define TPB 1024
#define NTW (NFFT / 4)                        // 4096 twiddles = 32 KB (L1-resident)
#define NPAD (NFFT + NFFT/16)
#define SMEM_BYTES (NPAD * sizeof(float2))    // 139264 B

// ---------------- device scratch ----------------
__device__ __half  g_xt[(size_t)B * D * L];   // x transposed [B][D][L], fp16
__device__ float   g_ht[(size_t)D * L];       // h transposed [D][L], fp32
__device__ __half2 g_hfh[(size_t)D * NFFT];   // H spectrum, fp16 complex (digit-reversed)
__device__ __half  g_yt[(size_t)B * D * L];   // y transposed [B][D][L], fp16
__device__ float2  g_tw[NTW];

// ---------------- helpers ----------------
__device__ __forceinline__ int pidx(int a) { return a + (a >> 4); }

__device__ __forceinline__ float2 cmul(float2 a, float2 b) {
    return make_float2(fmaf(a.x, b.x, -a.y * b.y),
                       fmaf(a.x, b.y,  a.y * b.x));
}
__device__ __forceinline__ float2 cadd(float2 a, float2 b) { return make_float2(a.x + b.x, a.y + b.y); }
__device__ __forceinline__ float2 csub(float2 a, float2 b) { return make_float2(a.x - b.x, a.y - b.y); }

__device__ __forceinline__ void bf4_dif(float2& a0, float2& a1, float2& a2, float2& a3) {
    float2 t0 = cadd(a0, a2), t1 = csub(a0, a2);
    float2 t2 = cadd(a1, a3), t3 = csub(a1, a3);
    a0 = cadd(t0, t2);
    a2 = csub(t0, t2);
    a1 = make_float2(t1.x + t3.y, t1.y - t3.x);  // t1 - i*t3
    a3 = make_float2(t1.x - t3.y, t1.y + t3.x);  // t1 + i*t3
}
__device__ __forceinline__ void bf4_dit(float2& a0, float2& a1, float2& a2, float2& a3) {
    float2 t0 = cadd(a0, a2), t1 = csub(a0, a2);
    float2 t2 = cadd(a1, a3), t3 = csub(a1, a3);
    a0 = cadd(t0, t2);
    a2 = csub(t0, t2);
    a1 = make_float2(t1.x - t3.y, t1.y + t3.x);  // t1 + i*t3
    a3 = make_float2(t1.x + t3.y, t1.y - t3.x);  // t1 - i*t3
}

// base-4 digit reversal of 14 bits: bit-reverse then swap adjacent bit pairs
__device__ __forceinline__ int rev4_14(int x) {
    unsigned y = __brev((unsigned)x) >> 18;
    return (int)(((y & 0x2AAAu) >> 1) | ((y & 0x1555u) << 1));
}

// ---------------- init: twiddles ----------------
__global__ void init_kernel() {
    int k = blockIdx.x * blockDim.x + threadIdx.x;
    if (k < NTW) {
        float s, c;
        sincospif(-2.0f * (float)k / (float)NFFT, &s, &c);
        g_tw[k] = make_float2(c, s);
    }
}

#define TTW 132   // padded tile row width in floats (128 + 4)

// ---------------- fp32 transpose: in[R][C] -> out[C][R] (h path) ----------------
__global__ void transpose_kernel(const float* __restrict__ in, float* __restrict__ out,
                                 int R, int C) {
    __shared__ float t[32 * TTW];
    const size_t zoff = (size_t)blockIdx.z * (size_t)R * (size_t)C;
    const int cbase = blockIdx.x * 128;
    const int rbase = blockIdx.y * 32;
    const int x = threadIdx.x, y = threadIdx.y;

    const float4* __restrict__ in4 = (const float4*)(in + zoff);
#pragma unroll
    for (int it = 0; it < 4; it++) {
        const int r = y + 8 * it;
        float4 v = in4[((size_t)(rbase + r) * C + cbase) / 4 + x];
        *(float4*)&t[r * TTW + 4 * x] = v;
    }
    __syncthreads();

    float* __restrict__ outz = out + zoff;
#pragma unroll
    for (int it = 0; it < 4; it++) {
        const int c_loc = x + 32 * it;
        float4 v;
        v.x = t[(4 * y + 0) * TTW + c_loc];
        v.y = t[(4 * y + 1) * TTW + c_loc];
        v.z = t[(4 * y + 2) * TTW + c_loc];
        v.w = t[(4 * y + 3) * TTW + c_loc];
        *(float4*)&outz[(size_t)(cbase + c_loc) * R + rbase + 4 * y] = v;
    }
}

// ---------------- fp32 -> fp16 transpose: in[R][C] f32 -> out[C][R] f16 (x path) ----
__global__ void transpose_f32f16_kernel(const float* __restrict__ in, __half* __restrict__ out,
                                        int R, int C) {
    __shared__ float t[32 * TTW];
    const size_t zoff = (size_t)blockIdx.z * (size_t)R * (size_t)C;
    const int cbase = blockIdx.x * 128;
    const int rbase = blockIdx.y * 32;
    const int x = threadIdx.x, y = threadIdx.y;

    const float4* __restrict__ in4 = (const float4*)(in + zoff);
#pragma unroll
    for (int it = 0; it < 4; it++) {
        const int r = y + 8 * it;
        float4 v = in4[((size_t)(rbase + r) * C + cbase) / 4 + x];
        *(float4*)&t[r * TTW + 4 * x] = v;
    }
    __syncthreads();

    __half* __restrict__ outz = out + zoff;
#pragma unroll
    for (int it = 0; it < 4; it++) {
        const int c_loc = x + 32 * it;
        __half2 h01 = __floats2half2_rn(t[(4 * y + 0) * TTW + c_loc],
                                        t[(4 * y + 1) * TTW + c_loc]);
        __half2 h23 = __floats2half2_rn(t[(4 * y + 2) * TTW + c_loc],
                                        t[(4 * y + 3) * TTW + c_loc]);
        uint2 packed = make_uint2(*(const unsigned*)&h01, *(const unsigned*)&h23);
        *(uint2*)&outz[(size_t)(cbase + c_loc) * R + rbase + 4 * y] = packed;
    }
}

// ---------------- fp16 -> fp32 transpose: in[R][C] f16 -> out[C][R] f32 (y path) ----
__global__ void transpose_f16f32_kernel(const __half* __restrict__ in, float* __restrict__ out,
                                        int R, int C) {
    __shared__ float t[32 * TTW];
    const size_t zoff = (size_t)blockIdx.z * (size_t)R * (size_t)C;
    const int cbase = blockIdx.x * 128;
    const int rbase = blockIdx.y * 32;
    const int x = threadIdx.x, y = threadIdx.y;

    const __half* __restrict__ inz = in + zoff;
#pragma unroll
    for (int it = 0; it < 4; it++) {
        const int r = y + 8 * it;
        uint2 raw = *(const uint2*)&inz[(size_t)(rbase + r) * C + cbase + 4 * x];
        float2 f01 = __half22float2(*(const __half2*)&raw.x);
        float2 f23 = __half22float2(*(const __half2*)&raw.y);
        *(float4*)&t[r * TTW + 4 * x] = make_float4(f01.x, f01.y, f23.x, f23.y);
    }
    __syncthreads();

    float* __restrict__ outz = out + zoff;
#pragma unroll
    for (int it = 0; it < 4; it++) {
        const int c_loc = x + 32 * it;
        float4 v;
        v.x = t[(4 * y + 0) * TTW + c_loc];
        v.y = t[(4 * y + 1) * TTW + c_loc];
        v.z = t[(4 * y + 2) * TTW + c_loc];
        v.w = t[(4 * y + 3) * TTW + c_loc];
        *(float4*)&outz[(size_t)(cbase + c_loc) * R + rbase + 4 * y] = v;
    }
}

// ---------------- fused first fwd stage (14+12) straight from gmem, fp32 rows ------
__device__ __forceinline__ void stageA_fwd_f32(const float* __restrict__ row0,
                                               const float* __restrict__ row1,
                                               float2* sd, int tid) {
    float2 v[4][4];
    const int pb = tid + (tid >> 4);
#pragma unroll
    for (int r = 0; r < 4; r++) {
        const int i0 = tid + r * 1024;
        const int i1 = i0 + 4096;
        float2 a0 = make_float2(__ldcs(row0 + i0), __ldcs(row1 + i0));
        float2 a1 = make_float2(__ldcs(row0 + i1), __ldcs(row1 + i1));
        float2 X0 = cadd(a0, a1);
        float2 X2 = csub(a0, a1);
        float2 X1 = make_float2(a0.x + a1.y, a0.y - a1.x);
        float2 X3 = make_float2(a0.x - a1.y, a0.y + a1.x);
        float2 w  = g_tw[tid + r * 1024];
        float2 w2 = cmul(w, w);
        float2 w3 = cmul(w2, w);
        v[r][0] = X0;
        v[r][1] = cmul(X1, w);
        v[r][2] = cmul(X2, w2);
        v[r][3] = cmul(X3, w3);
    }
    {
        float2 wb  = g_tw[4 * tid];
        float2 wb2 = cmul(wb, wb);
        float2 wb3 = cmul(wb2, wb);
#pragma unroll
        for (int s = 0; s < 4; s++) {
            bf4_dif(v[0][s], v[1][s], v[2][s], v[3][s]);
            v[1][s] = cmul(v[1][s], wb);
            v[2][s] = cmul(v[2][s], wb2);
            v[3][s] = cmul(v[3][s], wb3);
        }
    }
#pragma unroll
    for (int r = 0; r < 4; r++)
#pragma unroll
        for (int s = 0; s < 4; s++) {
            const int off = r * 1024 + s * 4096;
            sd[pb + off + (off >> 4)] = v[r][s];
        }
}

// ---------------- fused first fwd stage, fp16 rows (conv) ----------------
__device__ __forceinline__ void stageA_fwd_f16(const __half* __restrict__ row0,
                                               const __half* __restrict__ row1,
                                               float2* sd, int tid) {
    float2 v[4][4];
    const int pb = tid + (tid >> 4);
#pragma unroll
    for (int r = 0; r < 4; r++) {
        const int i0 = tid + r * 1024;
        const int i1 = i0 + 4096;
        float2 a0 = make_float2(__half2float(row0[i0]), __half2float(row1[i0]));
        float2 a1 = make_float2(__half2float(row0[i1]), __half2float(row1[i1]));
        float2 X0 = cadd(a0, a1);
        float2 X2 = csub(a0, a1);
        float2 X1 = make_float2(a0.x + a1.y, a0.y - a1.x);
        float2 X3 = make_float2(a0.x - a1.y, a0.y + a1.x);
        float2 w  = g_tw[tid + r * 1024];
        float2 w2 = cmul(w, w);
        float2 w3 = cmul(w2, w);
        v[r][0] = X0;
        v[r][1] = cmul(X1, w);
        v[r][2] = cmul(X2, w2);
        v[r][3] = cmul(X3, w3);
    }
    {
        float2 wb  = g_tw[4 * tid];
        float2 wb2 = cmul(wb, wb);
        float2 wb3 = cmul(wb2, wb);
#pragma unroll
        for (int s = 0; s < 4; s++) {
            bf4_dif(v[0][s], v[1][s], v[2][s], v[3][s]);
            v[1][s] = cmul(v[1][s], wb);
            v[2][s] = cmul(v[2][s], wb2);
            v[3][s] = cmul(v[3][s], wb3);
        }
    }
#pragma unroll
    for (int r = 0; r < 4; r++)
#pragma unroll
        for (int s = 0; s < 4; s++) {
            const int off = r * 1024 + s * 4096;
            sd[pb + off + (off >> 4)] = v[r][s];
        }
}

// ---------------- combined DIF stages (LS, LS-2), smem in/out ----------------
template<int LS>
__device__ __forceinline__ void dif_pair(float2* sd, int tid) {
    constexpr int Q2 = 1 << (LS - 4);
    constexpr int Q  = 1 << (LS - 2);
    constexpr int S  = 1 << (14 - LS);
    __syncthreads();
    const int j2 = tid & (Q2 - 1);
    const int g  = tid >> (LS - 4);
    const int base = (g << LS) + j2;
    const int pb = base + (base >> 4);
    float2 v[4][4];
#pragma unroll
    for (int r = 0; r < 4; r++)
#pragma unroll
        for (int s = 0; s < 4; s++) {
            const int off = r * Q2 + s * Q;
            v[r][s] = sd[pb + off + (off >> 4)];
        }
#pragma unroll
    for (int r = 0; r < 4; r++) {
        bf4_dif(v[r][0], v[r][1], v[r][2], v[r][3]);
        float2 w  = g_tw[(j2 + r * Q2) * S];
        float2 w2 = cmul(w, w);
        float2 w3 = cmul(w2, w);
        v[r][1] = cmul(v[r][1], w);
        v[r][2] = cmul(v[r][2], w2);
        v[r][3] = cmul(v[r][3], w3);
    }
    {
        float2 wb  = g_tw[j2 * (4 * S)];
        float2 wb2 = cmul(wb, wb);
        float2 wb3 = cmul(wb2, wb);
#pragma unroll
        for (int s = 0; s < 4; s++) {
            bf4_dif(v[0][s], v[1][s], v[2][s], v[3][s]);
            v[1][s] = cmul(v[1][s], wb);
            v[2][s] = cmul(v[2][s], wb2);
            v[3][s] = cmul(v[3][s], wb3);
        }
    }
#pragma unroll
    for (int r = 0; r < 4; r++)
#pragma unroll
        for (int s = 0; s < 4; s++) {
            const int off = r * Q2 + s * Q;
            sd[pb + off + (off >> 4)] = v[r][s];
        }
}

// final DIF stage ls=2 (hfft only)
__device__ __forceinline__ void dif_last(float2* sd, int tid) {
    __syncthreads();
#pragma unroll
    for (int tt = 0; tt < (NFFT / 4) / TPB; ++tt) {
        int t = tid + tt * TPB;
        int pb = 4 * t + (t >> 2);
        float2 a0 = sd[pb + 0];
        float2 a1 = sd[pb + 1];
        float2 a2 = sd[pb + 2];
        float2 a3 = sd[pb + 3];
        bf4_dif(a0, a1, a2, a3);
        sd[pb + 0] = a0;
        sd[pb + 1] = a1;
        sd[pb + 2] = a2;
        sd[pb + 3] = a3;
    }
}

// combined DIT stages (LSA, LSA+2), smem in/out
template<int LSA>
__device__ __forceinline__ void dit_pair(float2* sd, int tid) {
    constexpr int QA   = 1 << (LSA - 2);
    constexpr int SA   = 1 << (14 - LSA);
    constexpr int QB   = 1 << LSA;
    constexpr int SB   = SA >> 2;
    constexpr int LENB = 1 << (LSA + 2);
    __syncthreads();
    const int j = tid & (QA - 1);
    const int G = tid >> (LSA - 2);
    const int base = G * LENB + j;
    const int pb = base + (base >> 4);
    float2 v[4][4];
#pragma unroll
    for (int r = 0; r < 4; r++)
#pragma unroll
        for (int s = 0; s < 4; s++) {
            const int off = r * QA + s * QB;
            v[r][s] = sd[pb + off + (off >> 4)];
        }
    {
        float2 w   = g_tw[j * SA];
        float2 wc  = make_float2(w.x, -w.y);
        float2 wc2 = cmul(wc, wc);
        float2 wc3 = cmul(wc2, wc);
#pragma unroll
        for (int s = 0; s < 4; s++) {
            v[1][s] = cmul(v[1][s], wc);
            v[2][s] = cmul(v[2][s], wc2);
            v[3][s] = cmul(v[3][s], wc3);
            bf4_dit(v[0][s], v[1][s], v[2][s], v[3][s]);
        }
    }
#pragma unroll
    for (int r = 0; r < 4; r++) {
        float2 w   = g_tw[(j + r * QA) * SB];
        float2 wc  = make_float2(w.x, -w.y);
        float2 wc2 = cmul(wc, wc);
        float2 wc3 = cmul(wc2, wc);
        v[r][1] = cmul(v[r][1], wc);
        v[r][2] = cmul(v[r][2], wc2);
        v[r][3] = cmul(v[r][3], wc3);
        bf4_dit(v[r][0], v[r][1], v[r][2], v[r][3]);
    }
#pragma unroll
    for (int r = 0; r < 4; r++)
#pragma unroll
        for (int s = 0; s < 4; s++) {
            const int off = r * QA + s * QB;
            sd[pb + off + (off >> 4)] = v[r][s];
        }
}

// ---------------- H spectra: TWO channels per block via Hermitian split, fp16 out ----
__global__ __launch_bounds__(TPB, 1)
void hfft_kernel() {
    extern __shared__ float2 sd[];
    const int tid = threadIdx.x;
    const int d0  = 2 * blockIdx.x;
    const int d1  = d0 + 1;

    stageA_fwd_f32(g_ht + (size_t)d0 * L, g_ht + (size_t)d1 * L, sd, tid);
    dif_pair<10>(sd, tid);
    dif_pair<6>(sd, tid);
    dif_last(sd, tid);
    __syncthreads();

    __half2* __restrict__ hf0 = g_hfh + (size_t)d0 * NFFT;
    __half2* __restrict__ hf1 = g_hfh + (size_t)d1 * NFFT;
#pragma unroll
    for (int tt = 0; tt < NFFT / TPB; ++tt) {
        int p = tid + tt * TPB;
        int q = rev4_14((NFFT - rev4_14(p)) & (NFFT - 1));
        float2 zp = sd[p + (p >> 4)];
        float2 zq = sd[q + (q >> 4)];
        hf0[p] = __floats2half2_rn(0.5f * (zp.x + zq.x), 0.5f * (zp.y - zq.y));
        hf1[p] = __floats2half2_rn(0.5f * (zp.y + zq.y), 0.5f * (zq.x - zp.x));
    }
}

// ---------------- conv: one channel per block, both batches packed re/im ----------------
__global__ __launch_bounds__(TPB, 1)
void conv_kernel(const float* __restrict__ bias) {
    extern __shared__ float2 sd[];
    const int tid = threadIdx.x;
    const int d   = blockIdx.x;

    // fwd: fused first stage from gmem (fp16 x), then two smem pair-stages
    stageA_fwd_f16(g_xt + (size_t)d * L, g_xt + (size_t)(D + d) * L, sd, tid);
    dif_pair<10>(sd, tid);
    dif_pair<6>(sd, tid);

    // fused: dif_last + pointwise *H (fp16) + dit_first  (all on slots 4t..4t+3)
    __syncthreads();
    const __half2* __restrict__ hfh = g_hfh + (size_t)d * NFFT;
#pragma unroll
    for (int tt = 0; tt < (NFFT / 4) / TPB; ++tt) {
        int t = tid + tt * TPB;
        int pb = 4 * t + (t >> 2);
        float2 a0 = sd[pb + 0];
        float2 a1 = sd[pb + 1];
        float2 a2 = sd[pb + 2];
        float2 a3 = sd[pb + 3];
        bf4_dif(a0, a1, a2, a3);
        uint4 raw = __ldcs((const uint4*)(hfh + 4 * t));
        a0 = cmul(a0, __half22float2(*(const __half2*)&raw.x));
        a1 = cmul(a1, __half22float2(*(const __half2*)&raw.y));
        a2 = cmul(a2, __half22float2(*(const __half2*)&raw.z));
        a3 = cmul(a3, __half22float2(*(const __half2*)&raw.w));
        bf4_dit(a0, a1, a2, a3);
        sd[pb + 0] = a0;
        sd[pb + 1] = a1;
        sd[pb + 2] = a2;
        sd[pb + 3] = a3;
    }

    dit_pair<4>(sd, tid);
    dit_pair<8>(sd, tid);

    // fused final inverse stage (12+14): smem -> registers -> gmem fp16 (idx < L only)
    __syncthreads();
    {
        const int pb = tid + (tid >> 4);
        float2 v[4][4];
#pragma unroll
        for (int r = 0; r < 4; r++)
#pragma unroll
            for (int s = 0; s < 4; s++) {
                const int off = r * 1024 + s * 4096;
                v[r][s] = sd[pb + off + (off >> 4)];
            }
        {
            float2 w   = g_tw[4 * tid];
            float2 wc  = make_float2(w.x, -w.y);
            float2 wc2 = cmul(wc, wc);
            float2 wc3 = cmul(wc2, wc);
#pragma unroll
            for (int s = 0; s < 4; s++) {
                v[1][s] = cmul(v[1][s], wc);
                v[2][s] = cmul(v[2][s], wc2);
                v[3][s] = cmul(v[3][s], wc3);
                bf4_dit(v[0][s], v[1][s], v[2][s], v[3][s]);
            }
        }
        const float invN = 1.0f / (float)NFFT;
        const float bd = bias[d];
        __half* __restrict__ y0 = g_yt + (size_t)d * L;
        __half* __restrict__ y1 = g_yt + (size_t)(D + d) * L;
#pragma unroll
        for (int r = 0; r < 4; r++) {
            float2 w   = g_tw[tid + r * 1024];
            float2 wc  = make_float2(w.x, -w.y);
            float2 wc2 = cmul(wc, wc);
            float2 wc3 = cmul(wc2, wc);
            v[r][1] = cmul(v[r][1], wc);
            v[r][2] = cmul(v[r][2], wc2);
            v[r][3] = cmul(v[r][3], wc3);
            bf4_dit(v[r][0], v[r][1], v[r][2], v[r][3]);
#pragma unroll
            for (int s = 0; s < 2; s++) {
                const int idx = tid + r * 1024 + s * 4096;
                y0[idx] = __float2half_rn(fmaf(v[r][s].x, invN, bd));
                y1[idx] = __float2half_rn(fmaf(v[r][s].y, invN, bd));
            }
        }
    }
}

// ---------------- launch ----------------
extern "C" void kernel_launch(void* const* d_in, const int* in_sizes, int n_in,
                              void* d_out, int out_size) {
    const float* x    = (const float*)d_in[0];
    const float* h    = (const float*)d_in[1];
    const float* bias = (const float*)d_in[2];
    float* out = (float*)d_out;

    void *xt_p, *ht_p, *yt_p;
    cudaGetSymbolAddress(&xt_p, g_xt);
    cudaGetSymbolAddress(&ht_p, g_ht);
    cudaGetSymbolAddress(&yt_p, g_yt);

    cudaFuncSetAttribute(hfft_kernel, cudaFuncAttributeMaxDynamicSharedMemorySize, SMEM_BYTES);
    cudaFuncSetAttribute(conv_kernel, cudaFuncAttributeMaxDynamicSharedMemorySize, SMEM_BYTES);

    init_kernel<<<8, 512>>>();
    // x: [L][D] fp32 per batch -> [D][L] fp16
    transpose_f32f16_kernel<<<dim3(D / 128, L / 32, B), dim3(32, 8)>>>(x, (__half*)xt_p, L, D);
    // h: [L][D] fp32 -> [D][L] fp32
    transpose_kernel<<<dim3(D / 128, L / 32, 1), dim3(32, 8)>>>(h, (float*)ht_p, L, D);
    hfft_kernel<<<D / 2, TPB, SMEM_BYTES>>>();
    conv_kernel<<<D, TPB, SMEM_BYTES>>>(bias);
    // y: [D][L] fp16 per batch -> [L][D] fp32
    transpose_f16f32_kernel<<<dim3(L / 128, D / 32, B), dim3(32, 8)>>>((const __half*)yt_p, out, D, L);
}